// round 5
// baseline (speedup 1.0000x reference)
#include <cuda_runtime.h>
#include <cuda_bf16.h>
#include <cstdint>

// ---------------------------------------------------------------------------
// MoE SwiGLU FFN, GB300 (plain sm_103 PTX target -> HMMA mma.sync.m16n8k16).
// 3-pass bf16 split: C = Ahi*Bhi + Ahi*Blo + Alo*Bhi  (fp32 accumulate).
// w1/w3 rows interleaved -> SwiGLU fused into GEMM1 epilogue (bf16 hi/lo out).
// Round 5: single __syncthreads per K-chunk (wait->sync->issue->compute),
// shared+routed merged into single GEMM launches (z = 0..7 routed, 8 shared),
// GEMM2 all-atomicAdd onto pre-zeroed out.
// ---------------------------------------------------------------------------

#define DIMD 1024
#define HID  2752
#define NEXP 8
#define NTOK 8192
#define CAP  8192
#define RT   16384
#define TMg  128
#define TNg  128
#define TKg  32
#define STG  3

typedef __nv_bfloat16 bf16;

// ------------------------- scratch (device globals) ------------------------
__device__ int   g_cnt[NEXP];
__device__ int   g_off[NEXP + 1];
__device__ int   g_tok[NEXP * CAP];
__device__ float g_wt [NEXP * CAP];
__device__ int   g_rowtok[RT];
__device__ float g_rowwt [RT];

__device__ bf16 g_xhi [(size_t)NTOK * DIMD];
__device__ bf16 g_xlo [(size_t)NTOK * DIMD];
__device__ bf16 g_gxhi[(size_t)(RT + TMg) * DIMD];
__device__ bf16 g_gxlo[(size_t)(RT + TMg) * DIMD];
__device__ bf16 g_hhi [(size_t)(RT + TMg) * HID];      // routed hidden
__device__ bf16 g_hlo [(size_t)(RT + TMg) * HID];
__device__ bf16 g_shhi[(size_t)(NTOK + TMg) * HID];    // shared-expert hidden
__device__ bf16 g_shlo[(size_t)(NTOK + TMg) * HID];

// interleaved [w1 row j ; w3 row j] -> rows 2j, 2j+1
__device__ bf16 g_w13hi[(size_t)NEXP * 2 * HID * DIMD];
__device__ bf16 g_w13lo[(size_t)NEXP * 2 * HID * DIMD];
__device__ bf16 g_w2hi [(size_t)NEXP * DIMD * HID];
__device__ bf16 g_w2lo [(size_t)NEXP * DIMD * HID];
__device__ bf16 g_s13hi[(size_t)2 * HID * DIMD];
__device__ bf16 g_s13lo[(size_t)2 * HID * DIMD];
__device__ bf16 g_s2hi [(size_t)DIMD * HID];
__device__ bf16 g_s2lo [(size_t)DIMD * HID];

// ------------------------- PTX helpers -------------------------------------
__device__ __forceinline__ uint32_t smem_u32(const void* p) {
    uint32_t a;
    asm("{ .reg .u64 t; cvta.to.shared.u64 t, %1; cvt.u32.u64 %0, t; }"
        : "=r"(a) : "l"(p));
    return a;
}
__device__ __forceinline__ void cpa16(uint32_t dst, const void* src, uint32_t sz) {
    asm volatile("cp.async.cg.shared.global [%0], [%1], 16, %2;"
                 :: "r"(dst), "l"(src), "r"(sz));
}
#define CP_COMMIT() asm volatile("cp.async.commit_group;" ::: "memory")
#define CP_WAIT(n)  asm volatile("cp.async.wait_group %0;" :: "n"(n) : "memory")

__device__ __forceinline__ void ldsm4(uint32_t* r, uint32_t addr) {
    asm volatile("ldmatrix.sync.aligned.m8n8.x4.shared.b16 {%0,%1,%2,%3}, [%4];"
                 : "=r"(r[0]), "=r"(r[1]), "=r"(r[2]), "=r"(r[3]) : "r"(addr));
}
__device__ __forceinline__ void ldsm2(uint32_t* r, uint32_t addr) {
    asm volatile("ldmatrix.sync.aligned.m8n8.x2.shared.b16 {%0,%1}, [%2];"
                 : "=r"(r[0]), "=r"(r[1]) : "r"(addr));
}
__device__ __forceinline__ void mma16816(float* d, const uint32_t* a,
                                         const uint32_t* b) {
    asm volatile("mma.sync.aligned.m16n8k16.row.col.f32.bf16.bf16.f32 "
                 "{%0,%1,%2,%3}, {%4,%5,%6,%7}, {%8,%9}, {%0,%1,%2,%3};"
                 : "+f"(d[0]), "+f"(d[1]), "+f"(d[2]), "+f"(d[3])
                 : "r"(a[0]), "r"(a[1]), "r"(a[2]), "r"(a[3]),
                   "r"(b[0]), "r"(b[1]));
}
__device__ __forceinline__ uint32_t swz(int row, int chunk) {
    return (uint32_t)(row * 64 + ((chunk ^ ((row >> 1) & 3)) << 4));
}
__device__ __forceinline__ void split2(float v, bf16& h, bf16& l) {
    h = __float2bfloat16(v);
    l = __float2bfloat16(v - __bfloat162float(h));
}

// ------------------------- phase kernels -----------------------------------
__global__ void zero_out_kernel(float4* __restrict__ out) {
    out[blockIdx.x * 256 + threadIdx.x] = make_float4(0.f, 0.f, 0.f, 0.f);
}

__global__ void zero_kernel() {
    if (threadIdx.x < NEXP) g_cnt[threadIdx.x] = 0;
}

__global__ void route_kernel(const float* __restrict__ x,
                             const float* __restrict__ gw) {
    int warp = (blockIdx.x * blockDim.x + threadIdx.x) >> 5;
    int lane = threadIdx.x & 31;
    if (warp >= NTOK) return;
    const float* xr = x + (size_t)warp * DIMD;
    float xv[32];
#pragma unroll
    for (int i = 0; i < 32; i++) xv[i] = xr[i * 32 + lane];
    float logit[NEXP];
#pragma unroll
    for (int e = 0; e < NEXP; e++) {
        const float* g = gw + e * DIMD;
        float s = 0.f;
#pragma unroll
        for (int i = 0; i < 32; i++) s += xv[i] * g[i * 32 + lane];
#pragma unroll
        for (int o = 16; o; o >>= 1) s += __shfl_xor_sync(0xffffffffu, s, o);
        logit[e] = s;
    }
    float mx = logit[0];
#pragma unroll
    for (int e = 1; e < NEXP; e++) mx = fmaxf(mx, logit[e]);
    float p[NEXP], sum = 0.f;
#pragma unroll
    for (int e = 0; e < NEXP; e++) { p[e] = expf(logit[e] - mx); sum += p[e]; }
#pragma unroll
    for (int e = 0; e < NEXP; e++) p[e] /= sum;
    int i1 = 0;
#pragma unroll
    for (int e = 1; e < NEXP; e++) if (p[e] > p[i1]) i1 = e;
    int i2 = (i1 == 0) ? 1 : 0;
#pragma unroll
    for (int e = 0; e < NEXP; e++)
        if (e != i1 && e != i2 && p[e] > p[i2]) i2 = e;
    float d  = p[i1] + p[i2] + 1e-20f;
    float wa = p[i1] / d, wb = p[i2] / d;
    if (lane == 0) {
        int s1 = atomicAdd(&g_cnt[i1], 1);
        g_tok[i1 * CAP + s1] = warp; g_wt[i1 * CAP + s1] = wa;
        int s2 = atomicAdd(&g_cnt[i2], 1);
        g_tok[i2 * CAP + s2] = warp; g_wt[i2 * CAP + s2] = wb;
    }
}

__global__ void offsets_kernel() {
    if (threadIdx.x == 0) {
        int o = 0;
        for (int e = 0; e < NEXP; e++) { g_off[e] = o; o += g_cnt[e]; }
        g_off[NEXP] = o;
    }
}

// fp32 -> bf16 hi/lo split, vectorized by 4
__global__ void cvt_kernel(const float4* __restrict__ src,
                           uint2* __restrict__ hi, uint2* __restrict__ lo,
                           int n4) {
    int i = blockIdx.x * blockDim.x + threadIdx.x;
    if (i >= n4) return;
    float4 v = src[i];
    bf16 h0, h1, h2, h3, l0, l1, l2, l3;
    split2(v.x, h0, l0); split2(v.y, h1, l1);
    split2(v.z, h2, l2); split2(v.w, h3, l3);
    __nv_bfloat162 ha(h0, h1), hb(h2, h3), la(l0, l1), lb(l2, l3);
    uint2 H, L;
    H.x = *(const unsigned*)&ha; H.y = *(const unsigned*)&hb;
    L.x = *(const unsigned*)&la; L.y = *(const unsigned*)&lb;
    hi[i] = H; lo[i] = L;
}

// w1/w3 -> interleaved rows (2j, 2j+1) per logical row j
__global__ void cvt_ilv_kernel(const float4* __restrict__ w1,
                               const float4* __restrict__ w3,
                               uint2* __restrict__ hi, uint2* __restrict__ lo,
                               int nRows) {
    const int D4 = DIMD / 4;
    int i = blockIdx.x * blockDim.x + threadIdx.x;
    if (i >= nRows * D4) return;
    int r = i / D4, c = i % D4;
    int e = r / HID, j = r % HID;
    size_t d1 = ((size_t)(e * 2 * HID + 2 * j) * DIMD) / 4 + c;
    size_t d3 = d1 + D4;
#pragma unroll
    for (int s = 0; s < 2; s++) {
        float4 v = (s == 0) ? w1[i] : w3[i];
        bf16 h0, h1, h2, h3, l0, l1, l2, l3;
        split2(v.x, h0, l0); split2(v.y, h1, l1);
        split2(v.z, h2, l2); split2(v.w, h3, l3);
        __nv_bfloat162 ha(h0, h1), hb(h2, h3), la(l0, l1), lb(l2, l3);
        uint2 H, L;
        H.x = *(const unsigned*)&ha; H.y = *(const unsigned*)&hb;
        L.x = *(const unsigned*)&la; L.y = *(const unsigned*)&lb;
        size_t d = (s == 0) ? d1 : d3;
        hi[d] = H; lo[d] = L;
    }
}

__global__ void gather_kernel() {
    int e = blockIdx.y, i = blockIdx.x;
    int cnt = g_off[e + 1] - g_off[e];
    if (i >= cnt) return;
    int r = g_off[e] + i;
    int t = g_tok[e * CAP + i];
    const uint4* sh = (const uint4*)(g_xhi + (size_t)t * DIMD);
    const uint4* sl = (const uint4*)(g_xlo + (size_t)t * DIMD);
    uint4* dh = (uint4*)(g_gxhi + (size_t)r * DIMD);
    uint4* dl = (uint4*)(g_gxlo + (size_t)r * DIMD);
    int c = threadIdx.x;
    dh[c] = sh[c]; dl[c] = sl[c];
    if (c == 0) { g_rowtok[r] = t; g_rowwt[r] = g_wt[e * CAP + i]; }
}

// ------------------------- HMMA mainloop (shared) --------------------------
// Accumulates 3-pass split product into acc. Single __syncthreads per chunk:
// order = wait -> sync -> issue next stage -> compute (slot written at iter i
// held chunk i-1, consumed before the iter-i sync).
__device__ __forceinline__ void gemm_mainloop(
    uint32_t sb, const bf16* __restrict__ Ahi, const bf16* __restrict__ Alo,
    const bf16* __restrict__ bhi, const bf16* __restrict__ blo,
    int m0, int re, int n0, int N, int K, int tid, float acc[4][4][4]) {

    int wid = tid >> 5, lane = tid & 31;
    int wm = wid & 1, wn = wid >> 1;
    const int KN = K / TKg;
    const int nch = 3 * KN;

    auto load_chunk = [&](int ch, int stage) {
        int p = (ch >= 2 * KN) ? 2 : (ch >= KN ? 1 : 0);
        int k0 = (ch - p * KN) * TKg;
        const bf16* Ap = (p == 2) ? Alo : Ahi;
        const bf16* Bp = (p == 1) ? blo : bhi;
        uint32_t sA = sb + stage * 16384;
        uint32_t sB = sA + 8192;
#pragma unroll
        for (int t = 0; t < 2; t++) {
            int u = tid + t * 256;
            int row = u >> 2, c = u & 3;
            int gr = m0 + row;
            int grc = (gr < re) ? gr : m0;
            const char* src = (const char*)(Ap + (size_t)grc * K + k0 + c * 8);
            cpa16(sA + swz(row, c), src, (gr < re) ? 16u : 0u);
        }
#pragma unroll
        for (int t = 0; t < 2; t++) {
            int u = tid + t * 256;
            int row = u >> 2, c = u & 3;
            int gn = n0 + row;
            int gnc = (gn < N) ? gn : 0;
            const char* src = (const char*)(Bp + (size_t)gnc * K + k0 + c * 8);
            cpa16(sB + swz(row, c), src, (gn < N) ? 16u : 0u);
        }
        CP_COMMIT();
    };

#pragma unroll
    for (int s = 0; s < STG - 1; s++) load_chunk(s, s);

    for (int i = 0; i < nch; i++) {
        CP_WAIT(STG - 2);          // chunk i resident
        __syncthreads();           // all warps done with chunk i-1 (slot reuse)
        if (i + STG - 1 < nch) load_chunk(i + STG - 1, (i + STG - 1) % STG);
        else                   CP_COMMIT();   // keep group accounting aligned
        uint32_t sA = sb + (i % STG) * 16384;
        uint32_t sB = sA + 8192;
#pragma unroll
        for (int ks = 0; ks < 2; ks++) {
            uint32_t af[4][4], bfr[4][2];
#pragma unroll
            for (int mi = 0; mi < 4; mi++) {
                int row = wm * 64 + mi * 16 + (lane & 15);
                int c = ks * 2 + (lane >> 4);
                ldsm4(af[mi], sA + swz(row, c));
            }
#pragma unroll
            for (int nj = 0; nj < 4; nj++) {
                int row = wn * 32 + nj * 8 + (lane & 7);
                int c = ks * 2 + ((lane >> 3) & 1);
                ldsm2(bfr[nj], sB + swz(row, c));
            }
#pragma unroll
            for (int mi = 0; mi < 4; mi++)
#pragma unroll
                for (int nj = 0; nj < 4; nj++)
                    mma16816(acc[mi][nj], af[mi], bfr[nj]);
        }
    }
}

// ------------------------- GEMM1: x @ w13 -> swiglu -> hidden --------------
// z = 0..NEXP-1 routed (grouped rows, top-2 weight), z = NEXP shared expert.
__global__ __launch_bounds__(256, 2)
void hmma_gemm1() {
    __shared__ __align__(1024) char smc[STG * 16384];
    uint32_t sb = smem_u32(smc);

    int e = blockIdx.z;
    bool shexp = (e == NEXP);
    int rs, re;
    const bf16 *Ahi, *Alo, *bhi, *blo;
    bf16 *Hhi, *Hlo;
    if (shexp) {
        rs = 0; re = NTOK;
        Ahi = g_xhi; Alo = g_xlo;
        bhi = g_s13hi; blo = g_s13lo;
        Hhi = g_shhi; Hlo = g_shlo;
    } else {
        rs = g_off[e]; re = g_off[e + 1];
        Ahi = g_gxhi; Alo = g_gxlo;
        bhi = g_w13hi + (size_t)e * 2 * HID * DIMD;
        blo = g_w13lo + (size_t)e * 2 * HID * DIMD;
        Hhi = g_hhi; Hlo = g_hlo;
    }
    int m0 = rs + blockIdx.y * TMg;
    if (m0 >= re) return;
    int n0 = blockIdx.x * TNg;
    int tid = threadIdx.x;
    int wid = tid >> 5, lane = tid & 31;
    int wm = wid & 1, wn = wid >> 1;

    float acc[4][4][4];
#pragma unroll
    for (int a = 0; a < 4; a++)
#pragma unroll
        for (int b = 0; b < 4; b++)
#pragma unroll
            for (int c = 0; c < 4; c++) acc[a][b][c] = 0.f;

    gemm_mainloop(sb, Ahi, Alo, bhi, blo, m0, re, n0, 2 * HID, DIMD, tid, acc);

    // fused SwiGLU epilogue: even col = h (w1), odd col = g3 (w3)
#pragma unroll
    for (int mi = 0; mi < 4; mi++) {
#pragma unroll
        for (int h = 0; h < 2; h++) {
            int gr = m0 + wm * 64 + mi * 16 + (lane >> 2) + h * 8;
            if (gr >= re) continue;
            float w = shexp ? 1.0f : g_rowwt[gr];
            size_t rowoff = (size_t)gr * HID;
#pragma unroll
            for (int nj = 0; nj < 4; nj++) {
                int col = n0 + wn * 32 + nj * 8 + (lane & 3) * 2;
                int hidx = col >> 1;
                float hv = acc[mi][nj][h * 2 + 0];
                float gv = acc[mi][nj][h * 2 + 1];
                float v = w * (hv / (1.f + __expf(-hv))) * gv;
                bf16 hb, lb;
                split2(v, hb, lb);
                Hhi[rowoff + hidx] = hb;
                Hlo[rowoff + hidx] = lb;
            }
        }
    }
}

// ------------------------- GEMM2: hidden @ w2 -> +out (atomic) -------------
// z = 0..NEXP-1 routed (grouped rows, scatter via g_rowtok), z = NEXP shared.
__global__ __launch_bounds__(256, 2)
void hmma_gemm2(float* __restrict__ out) {
    __shared__ __align__(1024) char smc[STG * 16384];
    uint32_t sb = smem_u32(smc);

    int e = blockIdx.z;
    bool shexp = (e == NEXP);
    int rs, re;
    const bf16 *Ahi, *Alo, *bhi, *blo;
    if (shexp) {
        rs = 0; re = NTOK;
        Ahi = g_shhi; Alo = g_shlo;
        bhi = g_s2hi; blo = g_s2lo;
    } else {
        rs = g_off[e]; re = g_off[e + 1];
        Ahi = g_hhi; Alo = g_hlo;
        bhi = g_w2hi + (size_t)e * DIMD * HID;
        blo = g_w2lo + (size_t)e * DIMD * HID;
    }
    int m0 = rs + blockIdx.y * TMg;
    if (m0 >= re) return;
    int n0 = blockIdx.x * TNg;
    int tid = threadIdx.x;
    int wid = tid >> 5, lane = tid & 31;
    int wm = wid & 1, wn = wid >> 1;

    float acc[4][4][4];
#pragma unroll
    for (int a = 0; a < 4; a++)
#pragma unroll
        for (int b = 0; b < 4; b++)
#pragma unroll
            for (int c = 0; c < 4; c++) acc[a][b][c] = 0.f;

    gemm_mainloop(sb, Ahi, Alo, bhi, blo, m0, re, n0, DIMD, HID, tid, acc);

#pragma unroll
    for (int mi = 0; mi < 4; mi++) {
        int r0 = m0 + wm * 64 + mi * 16 + (lane >> 2);
#pragma unroll
        for (int h = 0; h < 2; h++) {
            int gr = r0 + h * 8;
            if (gr >= re) continue;
            size_t crow = shexp ? (size_t)gr * DIMD
                                : (size_t)g_rowtok[gr] * DIMD;
#pragma unroll
            for (int nj = 0; nj < 4; nj++) {
                int col = n0 + wn * 32 + nj * 8 + (lane & 3) * 2;
                atomicAdd(&out[crow + col],     acc[mi][nj][h * 2 + 0]);
                atomicAdd(&out[crow + col + 1], acc[mi][nj][h * 2 + 1]);
            }
        }
    }
}

// ------------------------- launch ------------------------------------------
static void cvt(const void* src, void* hi, void* lo, size_t n) {
    int n4 = (int)(n / 4);
    cvt_kernel<<<(n4 + 255) / 256, 256>>>((const float4*)src, (uint2*)hi,
                                          (uint2*)lo, n4);
}

extern "C" void kernel_launch(void* const* d_in, const int* in_sizes, int n_in,
                              void* d_out, int out_size) {
    const float* x      = (const float*)d_in[0];
    const float* gate_w = (const float*)d_in[1];
    const float* w1     = (const float*)d_in[2];
    const float* w3     = (const float*)d_in[3];
    const float* w2     = (const float*)d_in[4];
    const float* sw1    = (const float*)d_in[5];
    const float* sw3    = (const float*)d_in[6];
    const float* sw2    = (const float*)d_in[7];
    float* out = (float*)d_out;

    void *xhi, *xlo, *w13h, *w13l, *w2h, *w2l, *s13h, *s13l, *s2h, *s2l;
    cudaGetSymbolAddress(&xhi, g_xhi);    cudaGetSymbolAddress(&xlo, g_xlo);
    cudaGetSymbolAddress(&w13h, g_w13hi); cudaGetSymbolAddress(&w13l, g_w13lo);
    cudaGetSymbolAddress(&w2h, g_w2hi);   cudaGetSymbolAddress(&w2l, g_w2lo);
    cudaGetSymbolAddress(&s13h, g_s13hi); cudaGetSymbolAddress(&s13l, g_s13lo);
    cudaGetSymbolAddress(&s2h, g_s2hi);   cudaGetSymbolAddress(&s2l, g_s2lo);

    zero_out_kernel<<<(NTOK * DIMD / 4) / 256, 256>>>((float4*)out);
    zero_kernel<<<1, 32>>>();
    route_kernel<<<NTOK / 8, 256>>>(x, gate_w);
    offsets_kernel<<<1, 1>>>();

    cvt(x, xhi, xlo, (size_t)NTOK * DIMD);
    gather_kernel<<<dim3(CAP, NEXP), 128>>>();

    {   // routed w1/w3 interleaved
        int n = NEXP * HID * (DIMD / 4);
        cvt_ilv_kernel<<<(n + 255) / 256, 256>>>((const float4*)w1,
            (const float4*)w3, (uint2*)w13h, (uint2*)w13l, NEXP * HID);
    }
    {   // shared sw1/sw3 interleaved
        int n = HID * (DIMD / 4);
        cvt_ilv_kernel<<<(n + 255) / 256, 256>>>((const float4*)sw1,
            (const float4*)sw3, (uint2*)s13h, (uint2*)s13l, HID);
    }
    cvt(w2,  w2h, w2l, (size_t)NEXP * DIMD * HID);
    cvt(sw2, s2h, s2l, (size_t)DIMD * HID);

    const int NT_I = 2 * HID / TNg;           // 43
    const int NT_D = DIMD / TNg;              // 8
    const int MT   = NTOK / TMg;              // 64 (== CAP/TMg)

    // merged shared+routed launches: z = 0..7 routed experts, z = 8 shared
    hmma_gemm1<<<dim3(NT_I, MT, NEXP + 1), 256>>>();
    hmma_gemm2<<<dim3(NT_D, MT, NEXP + 1), 256>>>(out);
}